// round 1
// baseline (speedup 1.0000x reference)
#include <cuda_runtime.h>
#include <math.h>

#define NN 50000
#define EE 250000
#define GG 512

// ---------------- device scratch (allocation-free) ----------------
__device__ float g_out[NN * 32];          // node state (out == h)
__device__ float g_q[EE * 32];            // edge MLP hidden, in src-sorted order
__device__ float g_U[(size_t)NN * 1024];  // per-node U = out @ Wt   (204.8 MB)
__device__ float g_agg[NN * 32];          // scatter target
__device__ float g_bt[NN * 32];           // be2 bias term per node
__device__ float g_Wt[32 * 1024];         // Wt[h*1024 + k*32+o] = We2[k*1024 + h*32+o]
__device__ float g_WihT[32 * 96];         // WihT[h*96 + j] = Wih[j*32+h]
__device__ float g_WhhT[32 * 96];
__device__ int   g_hist[NN];
__device__ int   g_cursor[NN];
__device__ int   g_order[EE];
__device__ int   g_srcs[EE];
__device__ int   g_dsts[EE];
__device__ float g_deg[NN];               // in-degree (float, for mean)
__device__ float g_pooled[GG * 32];
__device__ float g_gcnt[GG];

#define FULL 0xffffffffu

// ---------------- kernels ----------------

__global__ void k_zero() {
    int i = blockIdx.x * blockDim.x + threadIdx.x;
    if (i < NN * 32) g_agg[i] = 0.f;
    if (i < NN)      { g_hist[i] = 0; g_deg[i] = 0.f; }
    if (i < GG * 32) g_pooled[i] = 0.f;
    if (i < GG)      g_gcnt[i] = 0.f;
}

// out = relu(x @ W0 + b0), warp per node
__global__ void k_lin0(const float* __restrict__ x, const float* __restrict__ W0,
                       const float* __restrict__ b0) {
    int gt = blockIdx.x * blockDim.x + threadIdx.x;
    int n = gt >> 5, lane = gt & 31;
    if (n >= NN) return;
    float xv = x[n * 32 + lane];
    float acc = __ldg(&b0[lane]);
#pragma unroll
    for (int i = 0; i < 32; i++)
        acc = fmaf(__shfl_sync(FULL, xv, i), __ldg(&W0[i * 32 + lane]), acc);
    g_out[n * 32 + lane] = fmaxf(acc, 0.f);
}

__global__ void k_hist(const int* __restrict__ ei) {
    int e = blockIdx.x * blockDim.x + threadIdx.x;
    if (e >= EE) return;
    atomicAdd(&g_hist[ei[e]], 1);          // src out-degree histogram (for sort)
    atomicAdd(&g_deg[ei[EE + e]], 1.f);    // dst in-degree (for mean)
}

// exclusive scan of g_hist into g_cursor, single block
__global__ void k_scan() {
    __shared__ int s[1024];
    __shared__ int carry;
    int t = threadIdx.x;
    if (t == 0) carry = 0;
    __syncthreads();
    for (int base = 0; base < NN; base += 1024) {
        int v = (base + t < NN) ? g_hist[base + t] : 0;
        s[t] = v;
        __syncthreads();
        for (int off = 1; off < 1024; off <<= 1) {
            int x = (t >= off) ? s[t - off] : 0;
            __syncthreads();
            s[t] += x;
            __syncthreads();
        }
        int excl = s[t] - v + carry;
        if (base + t < NN) g_cursor[base + t] = excl;
        __syncthreads();
        if (t == 1023) carry += s[1023];
        __syncthreads();
    }
}

__global__ void k_order(const int* __restrict__ ei) {
    int e = blockIdx.x * blockDim.x + threadIdx.x;
    if (e >= EE) return;
    int pos = atomicAdd(&g_cursor[ei[e]], 1);
    g_order[pos] = e;
}

// transposes: Wt, WihT, WhhT
__global__ void k_prep(const float* __restrict__ We2, const float* __restrict__ Wih,
                       const float* __restrict__ Whh) {
    int i = blockIdx.x * blockDim.x + threadIdx.x;
    if (i < 32 * 1024) {
        int h = i >> 10, c = i & 1023, k = c >> 5, o = c & 31;
        g_Wt[i] = We2[k * 1024 + h * 32 + o];
    }
    if (i < 32 * 96) {
        int h = i / 96, j = i % 96;
        g_WihT[i] = Wih[j * 32 + h];
        g_WhhT[i] = Whh[j * 32 + h];
    }
}

// q (edge MLP hidden) in sorted order + sorted src/dst
__global__ void k_permq(const float* __restrict__ ea, const int* __restrict__ ei,
                        const float* __restrict__ We1, const float* __restrict__ be1) {
    int gt = blockIdx.x * blockDim.x + threadIdx.x;
    int i = gt >> 5, lane = gt & 31;
    if (i >= EE) return;
    int e = g_order[i];
    float acc = __ldg(&be1[lane]);
#pragma unroll
    for (int t = 0; t < 16; t++)
        acc = fmaf(__ldg(&ea[e * 16 + t]), __ldg(&We1[t * 32 + lane]), acc);
    g_q[i * 32 + lane] = fmaxf(acc, 0.f);
    if (lane == 0) { g_srcs[i] = ei[e]; g_dsts[i] = ei[EE + e]; }
}

// U[n, k*32+o] = sum_h out[n,h] * Wt[h*1024 + k*32+o]
// block: 32 nodes x 256 cols, 8 warps; warp: 4 nodes x 256 cols; thread: 4 nodes x 8 cols
__global__ void k_u() {
    __shared__ float s_out[32][33];
    int n0 = blockIdx.x * 32;
    int c0 = blockIdx.y * 256;
    int t = threadIdx.x, lane = t & 31, w = t >> 5;
    for (int idx = t; idx < 1024; idx += 256) {
        int nn2 = idx >> 5, hh = idx & 31;
        int n = n0 + nn2;
        s_out[nn2][hh] = (n < NN) ? g_out[n * 32 + hh] : 0.f;
    }
    __syncthreads();
    int cbase = c0 + lane * 8;
    float acc[4][8];
#pragma unroll
    for (int r = 0; r < 4; r++)
#pragma unroll
        for (int j = 0; j < 8; j++) acc[r][j] = 0.f;
#pragma unroll
    for (int h = 0; h < 32; h++) {
        const float4 wa = *(const float4*)(g_Wt + h * 1024 + cbase);
        const float4 wb = *(const float4*)(g_Wt + h * 1024 + cbase + 4);
        float wv[8] = {wa.x, wa.y, wa.z, wa.w, wb.x, wb.y, wb.z, wb.w};
#pragma unroll
        for (int r = 0; r < 4; r++) {
            float ov = s_out[w * 4 + r][h];
#pragma unroll
            for (int j = 0; j < 8; j++) acc[r][j] = fmaf(ov, wv[j], acc[r][j]);
        }
    }
#pragma unroll
    for (int r = 0; r < 4; r++) {
        int n = n0 + w * 4 + r;
        if (n < NN) {
            *(float4*)(g_U + (size_t)n * 1024 + cbase) =
                make_float4(acc[r][0], acc[r][1], acc[r][2], acc[r][3]);
            *(float4*)(g_U + (size_t)n * 1024 + cbase + 4) =
                make_float4(acc[r][4], acc[r][5], acc[r][6], acc[r][7]);
        }
    }
}

// bias term: bt[n,o] = sum_h out[n,h]*be2[h*32+o]
__global__ void k_bt(const float* __restrict__ be2) {
    int gt = blockIdx.x * blockDim.x + threadIdx.x;
    int n = gt >> 5, lane = gt & 31;
    if (n >= NN) return;
    float ov = g_out[n * 32 + lane];
    float acc = 0.f;
#pragma unroll
    for (int h = 0; h < 32; h++)
        acc = fmaf(__shfl_sync(FULL, ov, h), __ldg(&be2[h * 32 + lane]), acc);
    g_bt[n * 32 + lane] = acc;
}

// msg[e,o] = bt[src,o] + sum_k q[e,k]*U[src,k*32+o]; scatter-add to agg[dst]
__global__ void k_edge() {
    int gt = blockIdx.x * blockDim.x + threadIdx.x;
    int i = gt >> 5, lane = gt & 31;
    if (i >= EE) return;
    int s = g_srcs[i];
    int d = g_dsts[i];
    const float* Ub = g_U + (size_t)s * 1024;
    const float* qb = g_q + i * 32;
    float acc = g_bt[s * 32 + lane];
#pragma unroll
    for (int k = 0; k < 32; k++)
        acc = fmaf(__ldg(&qb[k]), __ldg(&Ub[k * 32 + lane]), acc);
    atomicAdd(&g_agg[d * 32 + lane], acc);
}

// mean, root-linear, relu, GRU step; re-zeroes agg for next iter
__global__ void k_combine(const float* __restrict__ Wroot, const float* __restrict__ bconv,
                          const float* __restrict__ bih, const float* __restrict__ bhh) {
    int gt = blockIdx.x * blockDim.x + threadIdx.x;
    int n = gt >> 5, lane = gt & 31;
    if (n >= NN) return;
    float aggv = g_agg[n * 32 + lane];
    g_agg[n * 32 + lane] = 0.f;
    float mean = aggv / fmaxf(g_deg[n], 1.f);
    float hv = g_out[n * 32 + lane];
    float acc = __ldg(&bconv[lane]) + mean;
#pragma unroll
    for (int h = 0; h < 32; h++)
        acc = fmaf(__shfl_sync(FULL, hv, h), __ldg(&Wroot[h * 32 + lane]), acc);
    float m = fmaxf(acc, 0.f);
    float gr = __ldg(&bih[lane]), gz = __ldg(&bih[32 + lane]), gn = __ldg(&bih[64 + lane]);
    float hr = __ldg(&bhh[lane]), hz = __ldg(&bhh[32 + lane]), hn = __ldg(&bhh[64 + lane]);
#pragma unroll
    for (int h = 0; h < 32; h++) {
        float mh = __shfl_sync(FULL, m, h);
        float hh2 = __shfl_sync(FULL, hv, h);
        const float* wi = g_WihT + h * 96;
        const float* wh = g_WhhT + h * 96;
        gr = fmaf(mh, __ldg(&wi[lane]), gr);
        gz = fmaf(mh, __ldg(&wi[32 + lane]), gz);
        gn = fmaf(mh, __ldg(&wi[64 + lane]), gn);
        hr = fmaf(hh2, __ldg(&wh[lane]), hr);
        hz = fmaf(hh2, __ldg(&wh[32 + lane]), hz);
        hn = fmaf(hh2, __ldg(&wh[64 + lane]), hn);
    }
    float r = 1.f / (1.f + __expf(-(gr + hr)));
    float z = 1.f / (1.f + __expf(-(gz + hz)));
    float nn2 = tanhf(gn + r * hn);
    g_out[n * 32 + lane] = (1.f - z) * nn2 + z * hv;
}

__global__ void k_pool(const int* __restrict__ batch) {
    int gt = blockIdx.x * blockDim.x + threadIdx.x;
    int n = gt >> 5, lane = gt & 31;
    if (n >= NN) return;
    int b = __ldg(&batch[n]);
    atomicAdd(&g_pooled[b * 32 + lane], g_out[n * 32 + lane]);
    if (lane == 0) atomicAdd(&g_gcnt[b], 1.f);
}

__global__ void k_head(const float* __restrict__ W1a, const float* __restrict__ b1a,
                       const float* __restrict__ W1b, const float* __restrict__ b1b,
                       const float* __restrict__ W2a, const float* __restrict__ b2a,
                       const float* __restrict__ W2b, const float* __restrict__ b2b,
                       float* __restrict__ out, int out_size) {
    int gt = blockIdx.x * blockDim.x + threadIdx.x;
    int g = gt >> 5, lane = gt & 31;
    if (g >= GG) return;
    float c = fmaxf(g_gcnt[g], 1.f);
    float pm = g_pooled[g * 32 + lane] / c;
    float t1 = __ldg(&b1a[lane]);
    float t2 = __ldg(&b2a[lane]);
#pragma unroll
    for (int h = 0; h < 32; h++) {
        float ph = __shfl_sync(FULL, pm, h);
        t1 = fmaf(ph, __ldg(&W1a[h * 32 + lane]), t1);
        t2 = fmaf(ph, __ldg(&W2a[h * 32 + lane]), t2);
    }
    t1 = fmaxf(t1, 0.f);
    t2 = fmaxf(t2, 0.f);
    float lv = t1 * __ldg(&W1b[lane]);
    float d0 = t2 * __ldg(&W2b[lane * 2]);
    float d1 = t2 * __ldg(&W2b[lane * 2 + 1]);
#pragma unroll
    for (int off = 16; off; off >>= 1) {
        lv += __shfl_xor_sync(FULL, lv, off);
        d0 += __shfl_xor_sync(FULL, d0, off);
        d1 += __shfl_xor_sync(FULL, d1, off);
    }
    if (lane == 0) {
        float lab = lv + __ldg(&b1b[0]);
        float a0 = d0 + __ldg(&b2b[0]);
        float a1 = d1 + __ldg(&b2b[1]);
        float mx = fmaxf(a0, a1);
        float ls = mx + logf(expf(a0 - mx) + expf(a1 - mx));
        out[g] = lab;
        if (out_size >= GG * 3) {
            out[GG + g * 2]     = a0 - ls;
            out[GG + g * 2 + 1] = a1 - ls;
        }
    }
}

// ---------------- launch ----------------
extern "C" void kernel_launch(void* const* d_in, const int* in_sizes, int n_in,
                              void* d_out, int out_size) {
    const float* x     = (const float*)d_in[0];
    const float* ea    = (const float*)d_in[1];
    const int*   ei    = (const int*)d_in[2];
    const int*   batch = (const int*)d_in[3];
    // d_in[4] = alpha (unused in forward)
    const float* W0    = (const float*)d_in[5];
    const float* b0    = (const float*)d_in[6];
    const float* We1   = (const float*)d_in[7];
    const float* be1   = (const float*)d_in[8];
    const float* We2   = (const float*)d_in[9];
    const float* be2   = (const float*)d_in[10];
    const float* Wroot = (const float*)d_in[11];
    const float* bconv = (const float*)d_in[12];
    const float* Wih   = (const float*)d_in[13];
    const float* bih   = (const float*)d_in[14];
    const float* Whh   = (const float*)d_in[15];
    const float* bhh   = (const float*)d_in[16];
    const float* W1a   = (const float*)d_in[17];
    const float* b1a   = (const float*)d_in[18];
    const float* W1b   = (const float*)d_in[19];
    const float* b1b   = (const float*)d_in[20];
    const float* W2a   = (const float*)d_in[21];
    const float* b2a   = (const float*)d_in[22];
    const float* W2b   = (const float*)d_in[23];
    const float* b2b   = (const float*)d_in[24];
    float* out = (float*)d_out;

    const int TPB = 256;
    k_zero<<<(NN * 32 + TPB - 1) / TPB, TPB>>>();
    k_lin0<<<(NN * 32 + TPB - 1) / TPB, TPB>>>(x, W0, b0);
    k_hist<<<(EE + TPB - 1) / TPB, TPB>>>(ei);
    k_scan<<<1, 1024>>>();
    k_order<<<(EE + TPB - 1) / TPB, TPB>>>(ei);
    k_prep<<<(32 * 1024 + TPB - 1) / TPB, TPB>>>(We2, Wih, Whh);
    k_permq<<<((size_t)EE * 32 + TPB - 1) / TPB, TPB>>>(ea, ei, We1, be1);

    for (int it = 0; it < 3; it++) {
        k_u<<<dim3((NN + 31) / 32, 4), TPB>>>();
        k_bt<<<(NN * 32 + TPB - 1) / TPB, TPB>>>(be2);
        k_edge<<<((size_t)EE * 32 + TPB - 1) / TPB, TPB>>>();
        k_combine<<<(NN * 32 + TPB - 1) / TPB, TPB>>>(Wroot, bconv, bih, bhh);
    }

    k_pool<<<(NN * 32 + TPB - 1) / TPB, TPB>>>(batch);
    k_head<<<(GG * 32 + TPB - 1) / TPB, TPB>>>(W1a, b1a, W1b, b1b,
                                               W2a, b2a, W2b, b2b, out, out_size);
}

// round 3
// speedup vs baseline: 1.2255x; 1.2255x over previous
#include <cuda_runtime.h>
#include <math.h>

#define NN 50000
#define EE 250000
#define GG 512
#define NB_SCAN 49          // ceil(50000/1024)
#define NODES_PER_BLK 16
#define FUSE_GRID (NN / NODES_PER_BLK)   // 3125, exact

// ---------------- device scratch (allocation-free) ----------------
__device__ float g_out[NN * 32];          // node state (out == h)
__device__ float g_q[EE * 32];            // edge MLP hidden, src-sorted order
__device__ float g_agg[NN * 32];          // scatter target
__device__ float g_Wt[32 * 1024];         // Wt[h*1024 + k*32+o] = We2[k*1024 + h*32+o]
__device__ float g_WihT[32 * 96];
__device__ float g_WhhT[32 * 96];
__device__ int   g_hist[NN];
__device__ int   g_rowstart[NN];          // exclusive scan of hist (preserved)
__device__ int   g_cursor[NN];            // consumed by k_order
__device__ int   g_blocksum[NB_SCAN];
__device__ int   g_blockoff[NB_SCAN];
__device__ int   g_order[EE];
__device__ int   g_srcs[EE];
__device__ int   g_dsts[EE];
__device__ float g_deg[NN];
__device__ float g_pooled[GG * 32];
__device__ float g_gcnt[GG];

#define FULL 0xffffffffu

// ---------------- kernels ----------------

__global__ void k_zero() {
    int i = blockIdx.x * blockDim.x + threadIdx.x;
    if (i < NN * 32) g_agg[i] = 0.f;
    if (i < NN)      { g_hist[i] = 0; g_deg[i] = 0.f; }
    if (i < GG * 32) g_pooled[i] = 0.f;
    if (i < GG)      g_gcnt[i] = 0.f;
}

// out = relu(x @ W0 + b0), warp per node
__global__ void k_lin0(const float* __restrict__ x, const float* __restrict__ W0,
                       const float* __restrict__ b0) {
    int gt = blockIdx.x * blockDim.x + threadIdx.x;
    int n = gt >> 5, lane = gt & 31;
    if (n >= NN) return;
    float xv = x[n * 32 + lane];
    float acc = __ldg(&b0[lane]);
#pragma unroll
    for (int i = 0; i < 32; i++)
        acc = fmaf(__shfl_sync(FULL, xv, i), __ldg(&W0[i * 32 + lane]), acc);
    g_out[n * 32 + lane] = fmaxf(acc, 0.f);
}

__global__ void k_hist(const int* __restrict__ ei) {
    int e = blockIdx.x * blockDim.x + threadIdx.x;
    if (e >= EE) return;
    atomicAdd(&g_hist[ei[e]], 1);          // src out-degree (for sort)
    atomicAdd(&g_deg[ei[EE + e]], 1.f);    // dst in-degree (for mean)
}

// ---- fast 3-stage scan of g_hist -> g_rowstart / g_cursor ----
__global__ void k_scan_block() {
    __shared__ int s[1024];
    int t = threadIdx.x;
    int i = blockIdx.x * 1024 + t;
    int v = (i < NN) ? g_hist[i] : 0;
    s[t] = v;
    __syncthreads();
#pragma unroll
    for (int off = 1; off < 1024; off <<= 1) {
        int xv = (t >= off) ? s[t - off] : 0;
        __syncthreads();
        s[t] += xv;
        __syncthreads();
    }
    if (i < NN) g_rowstart[i] = s[t] - v;   // exclusive within block
    if (t == 1023) g_blocksum[blockIdx.x] = s[1023];
}

__global__ void k_scan_sums() {
    if (threadIdx.x == 0) {
        int acc = 0;
        for (int b = 0; b < NB_SCAN; b++) {
            g_blockoff[b] = acc;
            acc += g_blocksum[b];
        }
    }
}

__global__ void k_scan_add() {
    int i = blockIdx.x * blockDim.x + threadIdx.x;
    if (i >= NN) return;
    int v = g_rowstart[i] + g_blockoff[i >> 10];
    g_rowstart[i] = v;
    g_cursor[i] = v;
}

// writes g_order directly (device symbol referenced in DEVICE code only)
__global__ void k_order(const int* __restrict__ ei) {
    int e = blockIdx.x * blockDim.x + threadIdx.x;
    if (e >= EE) return;
    int pos = atomicAdd(&g_cursor[ei[e]], 1);
    g_order[pos] = e;
}

// transposes: Wt, WihT, WhhT
__global__ void k_prep(const float* __restrict__ We2, const float* __restrict__ Wih,
                       const float* __restrict__ Whh) {
    int i = blockIdx.x * blockDim.x + threadIdx.x;
    if (i < 32 * 1024) {
        int h = i >> 10, c = i & 1023, k = c >> 5, o = c & 31;
        g_Wt[i] = We2[k * 1024 + h * 32 + o];
    }
    if (i < 32 * 96) {
        int h = i / 96, j = i % 96;
        g_WihT[i] = Wih[j * 32 + h];
        g_WhhT[i] = Whh[j * 32 + h];
    }
}

// q (edge MLP hidden) in sorted order + sorted src/dst
__global__ void k_permq(const float* __restrict__ ea, const int* __restrict__ ei,
                        const float* __restrict__ We1, const float* __restrict__ be1) {
    int gt = blockIdx.x * blockDim.x + threadIdx.x;
    int i = gt >> 5, lane = gt & 31;
    if (i >= EE) return;
    int e = g_order[i];
    float acc = __ldg(&be1[lane]);
#pragma unroll
    for (int t = 0; t < 16; t++)
        acc = fmaf(__ldg(&ea[e * 16 + t]), __ldg(&We1[t * 32 + lane]), acc);
    g_q[i * 32 + lane] = fmaxf(acc, 0.f);
    if (lane == 0) { g_srcs[i] = ei[e]; g_dsts[i] = ei[EE + e]; }
}

// ---- FUSED: per-node U in SMEM + edge message + scatter ----
// block: 256 threads, 16 nodes. dyn smem: U[16][1024] + bt[16][32] + out[16][32]
__global__ void __launch_bounds__(256) k_fused(const float* __restrict__ be2) {
    extern __shared__ float sm[];
    float* U_s  = sm;                       // [16][1024]
    float* bt_s = sm + 16 * 1024;           // [16][32]
    float* o_s  = sm + 16 * 1024 + 16 * 32; // [16][32]

    int t = threadIdx.x, lane = t & 31, w = t >> 5;
    int n0 = blockIdx.x * NODES_PER_BLK;

    // load out tile: 512 floats, 256 threads -> 2 rounds
#pragma unroll
    for (int idx = t; idx < NODES_PER_BLK * 32; idx += 256)
        o_s[idx] = g_out[n0 * 32 + idx];
    __syncthreads();

    // bias term bt[n][o] = sum_h out[n,h]*be2[h*32+o]  (warp per node, 2 rounds)
#pragma unroll
    for (int r = 0; r < 2; r++) {
        int n = w + r * 8;
        float acc = 0.f;
#pragma unroll
        for (int h = 0; h < 32; h++)
            acc = fmaf(o_s[n * 32 + h], __ldg(&be2[h * 32 + lane]), acc);
        bt_s[n * 32 + lane] = acc;
    }

    // U: thread t owns cols 4t..4t+3 for all 16 nodes
    float4 acc[NODES_PER_BLK];
#pragma unroll
    for (int n = 0; n < NODES_PER_BLK; n++) acc[n] = make_float4(0.f, 0.f, 0.f, 0.f);
    const float4* Wt4 = (const float4*)g_Wt;
#pragma unroll
    for (int h = 0; h < 32; h++) {
        float4 wv = __ldg(&Wt4[h * 256 + t]);
#pragma unroll
        for (int n = 0; n < NODES_PER_BLK; n++) {
            float ov = o_s[n * 32 + h];
            acc[n].x = fmaf(ov, wv.x, acc[n].x);
            acc[n].y = fmaf(ov, wv.y, acc[n].y);
            acc[n].z = fmaf(ov, wv.z, acc[n].z);
            acc[n].w = fmaf(ov, wv.w, acc[n].w);
        }
    }
#pragma unroll
    for (int n = 0; n < NODES_PER_BLK; n++)
        *(float4*)(U_s + n * 1024 + 4 * t) = acc[n];
    __syncthreads();

    // edge phase: warp per edge over this block's contiguous (src-sorted) range
    int estart = g_rowstart[n0];
    int eend = (blockIdx.x == FUSE_GRID - 1) ? EE : g_rowstart[n0 + NODES_PER_BLK];
    for (int i = estart + w; i < eend; i += 8) {
        int sl = g_srcs[i] - n0;
        float qv = g_q[i * 32 + lane];
        const float* Ub = U_s + sl * 1024;
        float m = bt_s[sl * 32 + lane];
#pragma unroll
        for (int k = 0; k < 32; k++)
            m = fmaf(__shfl_sync(FULL, qv, k), Ub[k * 32 + lane], m);
        atomicAdd(&g_agg[g_dsts[i] * 32 + lane], m);
    }
}

// mean, root-linear, relu, GRU step; re-zeroes agg for next iter
__global__ void k_combine(const float* __restrict__ Wroot, const float* __restrict__ bconv,
                          const float* __restrict__ bih, const float* __restrict__ bhh) {
    int gt = blockIdx.x * blockDim.x + threadIdx.x;
    int n = gt >> 5, lane = gt & 31;
    if (n >= NN) return;
    float aggv = g_agg[n * 32 + lane];
    g_agg[n * 32 + lane] = 0.f;
    float mean = aggv / fmaxf(g_deg[n], 1.f);
    float hv = g_out[n * 32 + lane];
    float acc = __ldg(&bconv[lane]) + mean;
#pragma unroll
    for (int h = 0; h < 32; h++)
        acc = fmaf(__shfl_sync(FULL, hv, h), __ldg(&Wroot[h * 32 + lane]), acc);
    float m = fmaxf(acc, 0.f);
    float gr = __ldg(&bih[lane]), gz = __ldg(&bih[32 + lane]), gn = __ldg(&bih[64 + lane]);
    float hr = __ldg(&bhh[lane]), hz = __ldg(&bhh[32 + lane]), hn = __ldg(&bhh[64 + lane]);
#pragma unroll
    for (int h = 0; h < 32; h++) {
        float mh = __shfl_sync(FULL, m, h);
        float hh2 = __shfl_sync(FULL, hv, h);
        const float* wi = g_WihT + h * 96;
        const float* wh = g_WhhT + h * 96;
        gr = fmaf(mh, __ldg(&wi[lane]), gr);
        gz = fmaf(mh, __ldg(&wi[32 + lane]), gz);
        gn = fmaf(mh, __ldg(&wi[64 + lane]), gn);
        hr = fmaf(hh2, __ldg(&wh[lane]), hr);
        hz = fmaf(hh2, __ldg(&wh[32 + lane]), hz);
        hn = fmaf(hh2, __ldg(&wh[64 + lane]), hn);
    }
    float r = 1.f / (1.f + __expf(-(gr + hr)));
    float z = 1.f / (1.f + __expf(-(gz + hz)));
    float nn2 = tanhf(gn + r * hn);
    g_out[n * 32 + lane] = (1.f - z) * nn2 + z * hv;
}

__global__ void k_pool(const int* __restrict__ batch) {
    int gt = blockIdx.x * blockDim.x + threadIdx.x;
    int n = gt >> 5, lane = gt & 31;
    if (n >= NN) return;
    int b = __ldg(&batch[n]);
    atomicAdd(&g_pooled[b * 32 + lane], g_out[n * 32 + lane]);
    if (lane == 0) atomicAdd(&g_gcnt[b], 1.f);
}

__global__ void k_head(const float* __restrict__ W1a, const float* __restrict__ b1a,
                       const float* __restrict__ W1b, const float* __restrict__ b1b,
                       const float* __restrict__ W2a, const float* __restrict__ b2a,
                       const float* __restrict__ W2b, const float* __restrict__ b2b,
                       float* __restrict__ out, int out_size) {
    int gt = blockIdx.x * blockDim.x + threadIdx.x;
    int g = gt >> 5, lane = gt & 31;
    if (g >= GG) return;
    float c = fmaxf(g_gcnt[g], 1.f);
    float pm = g_pooled[g * 32 + lane] / c;
    float t1 = __ldg(&b1a[lane]);
    float t2 = __ldg(&b2a[lane]);
#pragma unroll
    for (int h = 0; h < 32; h++) {
        float ph = __shfl_sync(FULL, pm, h);
        t1 = fmaf(ph, __ldg(&W1a[h * 32 + lane]), t1);
        t2 = fmaf(ph, __ldg(&W2a[h * 32 + lane]), t2);
    }
    t1 = fmaxf(t1, 0.f);
    t2 = fmaxf(t2, 0.f);
    float lv = t1 * __ldg(&W1b[lane]);
    float d0 = t2 * __ldg(&W2b[lane * 2]);
    float d1 = t2 * __ldg(&W2b[lane * 2 + 1]);
#pragma unroll
    for (int off = 16; off; off >>= 1) {
        lv += __shfl_xor_sync(FULL, lv, off);
        d0 += __shfl_xor_sync(FULL, d0, off);
        d1 += __shfl_xor_sync(FULL, d1, off);
    }
    if (lane == 0) {
        float lab = lv + __ldg(&b1b[0]);
        float a0 = d0 + __ldg(&b2b[0]);
        float a1 = d1 + __ldg(&b2b[1]);
        float mx = fmaxf(a0, a1);
        float ls = mx + logf(expf(a0 - mx) + expf(a1 - mx));
        out[g] = lab;
        if (out_size >= GG * 3) {
            out[GG + g * 2]     = a0 - ls;
            out[GG + g * 2 + 1] = a1 - ls;
        }
    }
}

// ---------------- launch ----------------
extern "C" void kernel_launch(void* const* d_in, const int* in_sizes, int n_in,
                              void* d_out, int out_size) {
    const float* x     = (const float*)d_in[0];
    const float* ea    = (const float*)d_in[1];
    const int*   ei    = (const int*)d_in[2];
    const int*   batch = (const int*)d_in[3];
    const float* W0    = (const float*)d_in[5];
    const float* b0    = (const float*)d_in[6];
    const float* We1   = (const float*)d_in[7];
    const float* be1   = (const float*)d_in[8];
    const float* We2   = (const float*)d_in[9];
    const float* be2   = (const float*)d_in[10];
    const float* Wroot = (const float*)d_in[11];
    const float* bconv = (const float*)d_in[12];
    const float* Wih   = (const float*)d_in[13];
    const float* bih   = (const float*)d_in[14];
    const float* Whh   = (const float*)d_in[15];
    const float* bhh   = (const float*)d_in[16];
    const float* W1a   = (const float*)d_in[17];
    const float* b1a   = (const float*)d_in[18];
    const float* W1b   = (const float*)d_in[19];
    const float* b1b   = (const float*)d_in[20];
    const float* W2a   = (const float*)d_in[21];
    const float* b2a   = (const float*)d_in[22];
    const float* W2b   = (const float*)d_in[23];
    const float* b2b   = (const float*)d_in[24];
    float* out = (float*)d_out;

    const int TPB = 256;
    const int FUSE_SMEM = (16 * 1024 + 16 * 32 + 16 * 32) * 4;  // 69632 B
    static int smem_set = 0;
    if (!smem_set) {
        cudaFuncSetAttribute(k_fused, cudaFuncAttributeMaxDynamicSharedMemorySize, FUSE_SMEM);
        smem_set = 1;
    }

    k_zero<<<(NN * 32 + TPB - 1) / TPB, TPB>>>();
    k_lin0<<<(NN * 32 + TPB - 1) / TPB, TPB>>>(x, W0, b0);
    k_hist<<<(EE + TPB - 1) / TPB, TPB>>>(ei);
    k_scan_block<<<NB_SCAN, 1024>>>();
    k_scan_sums<<<1, 32>>>();
    k_scan_add<<<(NN + TPB - 1) / TPB, TPB>>>();
    k_order<<<(EE + TPB - 1) / TPB, TPB>>>(ei);
    k_prep<<<(32 * 1024 + TPB - 1) / TPB, TPB>>>(We2, Wih, Whh);
    k_permq<<<((size_t)EE * 32 + TPB - 1) / TPB, TPB>>>(ea, ei, We1, be1);

    for (int it = 0; it < 3; it++) {
        k_fused<<<FUSE_GRID, 256, FUSE_SMEM>>>(be2);
        k_combine<<<(NN * 32 + TPB - 1) / TPB, TPB>>>(Wroot, bconv, bih, bhh);
    }

    k_pool<<<(NN * 32 + TPB - 1) / TPB, TPB>>>(batch);
    k_head<<<(GG * 32 + TPB - 1) / TPB, TPB>>>(W1a, b1a, W1b, b1b,
                                               W2a, b2a, W2b, b2b, out, out_size);
}

// round 4
// speedup vs baseline: 1.6150x; 1.3178x over previous
#include <cuda_runtime.h>
#include <math.h>

#define NN 50000
#define EE 250000
#define GG 512
#define NB_SCAN 49          // ceil(50000/1024)
#define NODES_PER_BLK 16
#define FUSE_GRID (NN / NODES_PER_BLK)   // 3125, exact
#define FUSE_THREADS 512

// ---------------- device scratch (allocation-free) ----------------
__device__ float g_out[NN * 32];          // node state (out == h)
__device__ float g_q[EE * 32];            // edge MLP hidden, src-sorted order
__device__ float g_agg[NN * 32];          // scatter target
__device__ float g_Wt[32 * 1024];         // Wt[h*1024 + k*32+o] = We2[k*1024 + h*32+o]
__device__ float g_WihT[32 * 96];
__device__ float g_WhhT[32 * 96];
__device__ int   g_hist[NN];
__device__ int   g_rowstart[NN];          // exclusive scan of hist (preserved)
__device__ int   g_cursor[NN];            // consumed by k_order
__device__ int   g_blocksum[NB_SCAN];
__device__ int   g_blockoff[NB_SCAN];
__device__ int   g_order[EE];
__device__ int   g_srcs[EE];
__device__ int   g_dsts[EE];
__device__ float g_deg[NN];
__device__ float g_pooled[GG * 32];
__device__ float g_gcnt[GG];

#define FULL 0xffffffffu

// ---- packed f32x2 helpers (FFMA2: only reachable via PTX) ----
__device__ __forceinline__ void fma2(unsigned long long& d,
                                     unsigned long long a, unsigned long long b) {
    asm("fma.rn.f32x2 %0, %1, %2, %0;" : "+l"(d) : "l"(a), "l"(b));
}
__device__ __forceinline__ unsigned long long pack2(float lo, float hi) {
    unsigned long long r;
    asm("mov.b64 %0, {%1, %2};" : "=l"(r) : "f"(lo), "f"(hi));
    return r;
}
__device__ __forceinline__ float2 unpack2(unsigned long long v) {
    float2 f;
    asm("mov.b64 {%0, %1}, %2;" : "=f"(f.x), "=f"(f.y) : "l"(v));
    return f;
}

// ---------------- kernels ----------------

__global__ void k_zero() {
    int i = blockIdx.x * blockDim.x + threadIdx.x;
    if (i < NN * 32) g_agg[i] = 0.f;
    if (i < NN)      { g_hist[i] = 0; g_deg[i] = 0.f; }
    if (i < GG * 32) g_pooled[i] = 0.f;
    if (i < GG)      g_gcnt[i] = 0.f;
}

// out = relu(x @ W0 + b0), warp per node
__global__ void k_lin0(const float* __restrict__ x, const float* __restrict__ W0,
                       const float* __restrict__ b0) {
    int gt = blockIdx.x * blockDim.x + threadIdx.x;
    int n = gt >> 5, lane = gt & 31;
    if (n >= NN) return;
    float xv = x[n * 32 + lane];
    float acc = __ldg(&b0[lane]);
#pragma unroll
    for (int i = 0; i < 32; i++)
        acc = fmaf(__shfl_sync(FULL, xv, i), __ldg(&W0[i * 32 + lane]), acc);
    g_out[n * 32 + lane] = fmaxf(acc, 0.f);
}

__global__ void k_hist(const int* __restrict__ ei) {
    int e = blockIdx.x * blockDim.x + threadIdx.x;
    if (e >= EE) return;
    atomicAdd(&g_hist[ei[e]], 1);          // src out-degree (for sort)
    atomicAdd(&g_deg[ei[EE + e]], 1.f);    // dst in-degree (for mean)
}

// ---- fast 3-stage scan of g_hist -> g_rowstart / g_cursor ----
__global__ void k_scan_block() {
    __shared__ int s[1024];
    int t = threadIdx.x;
    int i = blockIdx.x * 1024 + t;
    int v = (i < NN) ? g_hist[i] : 0;
    s[t] = v;
    __syncthreads();
#pragma unroll
    for (int off = 1; off < 1024; off <<= 1) {
        int xv = (t >= off) ? s[t - off] : 0;
        __syncthreads();
        s[t] += xv;
        __syncthreads();
    }
    if (i < NN) g_rowstart[i] = s[t] - v;   // exclusive within block
    if (t == 1023) g_blocksum[blockIdx.x] = s[1023];
}

__global__ void k_scan_sums() {
    if (threadIdx.x == 0) {
        int acc = 0;
        for (int b = 0; b < NB_SCAN; b++) {
            g_blockoff[b] = acc;
            acc += g_blocksum[b];
        }
    }
}

__global__ void k_scan_add() {
    int i = blockIdx.x * blockDim.x + threadIdx.x;
    if (i >= NN) return;
    int v = g_rowstart[i] + g_blockoff[i >> 10];
    g_rowstart[i] = v;
    g_cursor[i] = v;
}

__global__ void k_order(const int* __restrict__ ei) {
    int e = blockIdx.x * blockDim.x + threadIdx.x;
    if (e >= EE) return;
    int pos = atomicAdd(&g_cursor[ei[e]], 1);
    g_order[pos] = e;
}

// transposes: Wt, WihT, WhhT
__global__ void k_prep(const float* __restrict__ We2, const float* __restrict__ Wih,
                       const float* __restrict__ Whh) {
    int i = blockIdx.x * blockDim.x + threadIdx.x;
    if (i < 32 * 1024) {
        int h = i >> 10, c = i & 1023, k = c >> 5, o = c & 31;
        g_Wt[i] = We2[k * 1024 + h * 32 + o];
    }
    if (i < 32 * 96) {
        int h = i / 96, j = i % 96;
        g_WihT[i] = Wih[j * 32 + h];
        g_WhhT[i] = Whh[j * 32 + h];
    }
}

// q (edge MLP hidden) in sorted order + sorted src/dst
__global__ void k_permq(const float* __restrict__ ea, const int* __restrict__ ei,
                        const float* __restrict__ We1, const float* __restrict__ be1) {
    int gt = blockIdx.x * blockDim.x + threadIdx.x;
    int i = gt >> 5, lane = gt & 31;
    if (i >= EE) return;
    int e = g_order[i];
    float acc = __ldg(&be1[lane]);
#pragma unroll
    for (int t = 0; t < 16; t++)
        acc = fmaf(__ldg(&ea[e * 16 + t]), __ldg(&We1[t * 32 + lane]), acc);
    g_q[i * 32 + lane] = fmaxf(acc, 0.f);
    if (lane == 0) { g_srcs[i] = ei[e]; g_dsts[i] = ei[EE + e]; }
}

// ---- FUSED: per-node U in SMEM (FFMA2) + 4-edge vectorized message + scatter ----
// 512 threads. smem: U[16][1024] | o_sT[32][20] | bt[16][32]
__global__ void __launch_bounds__(FUSE_THREADS) k_fused(const float* __restrict__ be2) {
    extern __shared__ float sm[];
    float* U_s  = sm;                        // 16384 floats
    float* o_sT = sm + 16 * 1024;            // [32][20] transposed, padded
    float* bt_s = sm + 16 * 1024 + 32 * 20;  // [16][32]

    int t = threadIdx.x, lane = t & 31, w = t >> 5;
    int n0 = blockIdx.x * NODES_PER_BLK;

    // load out tile transposed: o_sT[h][n]
    {
        int n = t >> 5, h = t & 31;
        o_sT[h * 20 + n] = g_out[n0 * 32 + t];
    }
    __syncthreads();

    // bias term bt[n][o] = sum_h out[n,h]*be2[h*32+o]  (warp w -> node w)
    {
        float acc = 0.f;
#pragma unroll
        for (int h = 0; h < 32; h++)
            acc = fmaf(o_sT[h * 20 + w], __ldg(&be2[h * 32 + lane]), acc);
        bt_s[w * 32 + lane] = acc;
    }

    // U phase: thread t owns cols (2t, 2t+1); accumulate over node-pairs with FFMA2
    {
        unsigned long long accA[8], accB[8];   // accA: col 2t, accB: col 2t+1; 8 node-pairs
#pragma unroll
        for (int p = 0; p < 8; p++) { accA[p] = 0ull; accB[p] = 0ull; }
        const float2* Wt2 = (const float2*)g_Wt;
#pragma unroll
        for (int h = 0; h < 32; h++) {
            float2 wv = __ldg(&Wt2[h * 512 + t]);
            unsigned long long wxx = pack2(wv.x, wv.x);
            unsigned long long wyy = pack2(wv.y, wv.y);
            const float* row = o_sT + h * 20;
#pragma unroll
            for (int q4 = 0; q4 < 4; q4++) {
                ulonglong2 ov = *(const ulonglong2*)(row + q4 * 4);  // (n0,n1),(n2,n3)
                fma2(accA[q4 * 2 + 0], ov.x, wxx);
                fma2(accA[q4 * 2 + 1], ov.y, wxx);
                fma2(accB[q4 * 2 + 0], ov.x, wyy);
                fma2(accB[q4 * 2 + 1], ov.y, wyy);
            }
        }
        // store: U_s[n*1024 + 2t .. 2t+1]
#pragma unroll
        for (int p = 0; p < 8; p++) {
            float2 a = unpack2(accA[p]);
            float2 b = unpack2(accB[p]);
            *(float2*)(U_s + (p * 2 + 0) * 1024 + 2 * t) = make_float2(a.x, b.x);
            *(float2*)(U_s + (p * 2 + 1) * 1024 + 2 * t) = make_float2(a.y, b.y);
        }
    }
    __syncthreads();

    // edge phase: 4 edges per warp iter; lane = (edge_local = lane>>3, osub = (lane&7)*4)
    int estart = g_rowstart[n0];
    int eend = (blockIdx.x == FUSE_GRID - 1) ? EE : g_rowstart[n0 + NODES_PER_BLK];
    int osub = (lane & 7) * 4;
    for (int base = estart + w * 4; base < eend; base += 16 * 4) {
        int e = base + (lane >> 3);
        bool valid = e < eend;
        int sl = 0, d = 0;
        float4 q4 = make_float4(0.f, 0.f, 0.f, 0.f);
        if (valid) {
            sl = g_srcs[e] - n0;
            d = g_dsts[e];
            q4 = *(const float4*)(g_q + (size_t)e * 32 + osub);
        }
        const float* Ub = U_s + sl * 1024 + osub;
        float4 m = *(const float4*)(bt_s + sl * 32 + osub);
#pragma unroll
        for (int k = 0; k < 32; k++) {
            float comp = (k & 3) == 0 ? q4.x : (k & 3) == 1 ? q4.y
                       : (k & 3) == 2 ? q4.z : q4.w;
            float qk = __shfl_sync(FULL, comp, (lane & 24) + (k >> 2));
            float4 uv = *(const float4*)(Ub + k * 32);
            m.x = fmaf(qk, uv.x, m.x);
            m.y = fmaf(qk, uv.y, m.y);
            m.z = fmaf(qk, uv.z, m.z);
            m.w = fmaf(qk, uv.w, m.w);
        }
        if (valid) {
            float* dst = g_agg + (size_t)d * 32 + osub;
            atomicAdd(dst + 0, m.x);
            atomicAdd(dst + 1, m.y);
            atomicAdd(dst + 2, m.z);
            atomicAdd(dst + 3, m.w);
        }
    }
}

// mean, root-linear, relu, GRU step; re-zeroes agg for next iter
__global__ void k_combine(const float* __restrict__ Wroot, const float* __restrict__ bconv,
                          const float* __restrict__ bih, const float* __restrict__ bhh) {
    int gt = blockIdx.x * blockDim.x + threadIdx.x;
    int n = gt >> 5, lane = gt & 31;
    if (n >= NN) return;
    float aggv = g_agg[n * 32 + lane];
    g_agg[n * 32 + lane] = 0.f;
    float mean = aggv / fmaxf(g_deg[n], 1.f);
    float hv = g_out[n * 32 + lane];
    float acc = __ldg(&bconv[lane]) + mean;
#pragma unroll
    for (int h = 0; h < 32; h++)
        acc = fmaf(__shfl_sync(FULL, hv, h), __ldg(&Wroot[h * 32 + lane]), acc);
    float m = fmaxf(acc, 0.f);
    float gr = __ldg(&bih[lane]), gz = __ldg(&bih[32 + lane]), gn = __ldg(&bih[64 + lane]);
    float hr = __ldg(&bhh[lane]), hz = __ldg(&bhh[32 + lane]), hn = __ldg(&bhh[64 + lane]);
#pragma unroll
    for (int h = 0; h < 32; h++) {
        float mh = __shfl_sync(FULL, m, h);
        float hh2 = __shfl_sync(FULL, hv, h);
        const float* wi = g_WihT + h * 96;
        const float* wh = g_WhhT + h * 96;
        gr = fmaf(mh, __ldg(&wi[lane]), gr);
        gz = fmaf(mh, __ldg(&wi[32 + lane]), gz);
        gn = fmaf(mh, __ldg(&wi[64 + lane]), gn);
        hr = fmaf(hh2, __ldg(&wh[lane]), hr);
        hz = fmaf(hh2, __ldg(&wh[32 + lane]), hz);
        hn = fmaf(hh2, __ldg(&wh[64 + lane]), hn);
    }
    float r = 1.f / (1.f + __expf(-(gr + hr)));
    float z = 1.f / (1.f + __expf(-(gz + hz)));
    float nn2 = tanhf(gn + r * hn);
    g_out[n * 32 + lane] = (1.f - z) * nn2 + z * hv;
}

__global__ void k_pool(const int* __restrict__ batch) {
    int gt = blockIdx.x * blockDim.x + threadIdx.x;
    int n = gt >> 5, lane = gt & 31;
    if (n >= NN) return;
    int b = __ldg(&batch[n]);
    atomicAdd(&g_pooled[b * 32 + lane], g_out[n * 32 + lane]);
    if (lane == 0) atomicAdd(&g_gcnt[b], 1.f);
}

__global__ void k_head(const float* __restrict__ W1a, const float* __restrict__ b1a,
                       const float* __restrict__ W1b, const float* __restrict__ b1b,
                       const float* __restrict__ W2a, const float* __restrict__ b2a,
                       const float* __restrict__ W2b, const float* __restrict__ b2b,
                       float* __restrict__ out, int out_size) {
    int gt = blockIdx.x * blockDim.x + threadIdx.x;
    int g = gt >> 5, lane = gt & 31;
    if (g >= GG) return;
    float c = fmaxf(g_gcnt[g], 1.f);
    float pm = g_pooled[g * 32 + lane] / c;
    float t1 = __ldg(&b1a[lane]);
    float t2 = __ldg(&b2a[lane]);
#pragma unroll
    for (int h = 0; h < 32; h++) {
        float ph = __shfl_sync(FULL, pm, h);
        t1 = fmaf(ph, __ldg(&W1a[h * 32 + lane]), t1);
        t2 = fmaf(ph, __ldg(&W2a[h * 32 + lane]), t2);
    }
    t1 = fmaxf(t1, 0.f);
    t2 = fmaxf(t2, 0.f);
    float lv = t1 * __ldg(&W1b[lane]);
    float d0 = t2 * __ldg(&W2b[lane * 2]);
    float d1 = t2 * __ldg(&W2b[lane * 2 + 1]);
#pragma unroll
    for (int off = 16; off; off >>= 1) {
        lv += __shfl_xor_sync(FULL, lv, off);
        d0 += __shfl_xor_sync(FULL, d0, off);
        d1 += __shfl_xor_sync(FULL, d1, off);
    }
    if (lane == 0) {
        float lab = lv + __ldg(&b1b[0]);
        float a0 = d0 + __ldg(&b2b[0]);
        float a1 = d1 + __ldg(&b2b[1]);
        float mx = fmaxf(a0, a1);
        float ls = mx + logf(expf(a0 - mx) + expf(a1 - mx));
        out[g] = lab;
        if (out_size >= GG * 3) {
            out[GG + g * 2]     = a0 - ls;
            out[GG + g * 2 + 1] = a1 - ls;
        }
    }
}

// ---------------- launch ----------------
extern "C" void kernel_launch(void* const* d_in, const int* in_sizes, int n_in,
                              void* d_out, int out_size) {
    const float* x     = (const float*)d_in[0];
    const float* ea    = (const float*)d_in[1];
    const int*   ei    = (const int*)d_in[2];
    const int*   batch = (const int*)d_in[3];
    const float* W0    = (const float*)d_in[5];
    const float* b0    = (const float*)d_in[6];
    const float* We1   = (const float*)d_in[7];
    const float* be1   = (const float*)d_in[8];
    const float* We2   = (const float*)d_in[9];
    const float* be2   = (const float*)d_in[10];
    const float* Wroot = (const float*)d_in[11];
    const float* bconv = (const float*)d_in[12];
    const float* Wih   = (const float*)d_in[13];
    const float* bih   = (const float*)d_in[14];
    const float* Whh   = (const float*)d_in[15];
    const float* bhh   = (const float*)d_in[16];
    const float* W1a   = (const float*)d_in[17];
    const float* b1a   = (const float*)d_in[18];
    const float* W1b   = (const float*)d_in[19];
    const float* b1b   = (const float*)d_in[20];
    const float* W2a   = (const float*)d_in[21];
    const float* b2a   = (const float*)d_in[22];
    const float* W2b   = (const float*)d_in[23];
    const float* b2b   = (const float*)d_in[24];
    float* out = (float*)d_out;

    const int TPB = 256;
    const int FUSE_SMEM = (16 * 1024 + 32 * 20 + 16 * 32) * 4;  // 70144 B
    cudaFuncSetAttribute(k_fused, cudaFuncAttributeMaxDynamicSharedMemorySize, FUSE_SMEM);

    k_zero<<<(NN * 32 + TPB - 1) / TPB, TPB>>>();
    k_lin0<<<(NN * 32 + TPB - 1) / TPB, TPB>>>(x, W0, b0);
    k_hist<<<(EE + TPB - 1) / TPB, TPB>>>(ei);
    k_scan_block<<<NB_SCAN, 1024>>>();
    k_scan_sums<<<1, 32>>>();
    k_scan_add<<<(NN + TPB - 1) / TPB, TPB>>>();
    k_order<<<(EE + TPB - 1) / TPB, TPB>>>(ei);
    k_prep<<<(32 * 1024 + TPB - 1) / TPB, TPB>>>(We2, Wih, Whh);
    k_permq<<<((size_t)EE * 32 + TPB - 1) / TPB, TPB>>>(ea, ei, We1, be1);

    for (int it = 0; it < 3; it++) {
        k_fused<<<FUSE_GRID, FUSE_THREADS, FUSE_SMEM>>>(be2);
        k_combine<<<(NN * 32 + TPB - 1) / TPB, TPB>>>(Wroot, bconv, bih, bhh);
    }

    k_pool<<<(NN * 32 + TPB - 1) / TPB, TPB>>>(batch);
    k_head<<<(GG * 32 + TPB - 1) / TPB, TPB>>>(W1a, b1a, W1b, b1b,
                                               W2a, b2a, W2b, b2b, out, out_size);
}